// round 16
// baseline (speedup 1.0000x reference)
#include <cuda_runtime.h>
#include <cuda_fp16.h>
#include <cstdint>

#define NNODES 100000
#define D      256
#define HID    256

// ---------------- device scratch (allocation-free rule) ----------------
__device__ __half g_A[(size_t)NNODES * HID];   // xs@W1top + b1  (fp16)
__device__ __half g_B[(size_t)NNODES * HID];   // xd@W1bot       (fp16)
// Transposed fp16 weights: Wt[z][n][k], z=0 src half, z=1 dst half
__device__ __half g_Wt[2 * 256 * 256];

// ---------------- helpers ----------------
__device__ __forceinline__ uint32_t smem_u32(const void* p) {
    uint32_t a;
    asm("{ .reg .u64 t; cvta.to.shared.u64 t, %1; cvt.u32.u64 %0, t; }"
        : "=r"(a) : "l"(p));
    return a;
}
__device__ __forceinline__ void ldsm4(uint32_t* r, uint32_t addr) {
    asm volatile("ldmatrix.sync.aligned.m8n8.x4.shared.b16 {%0,%1,%2,%3}, [%4];"
                 : "=r"(r[0]), "=r"(r[1]), "=r"(r[2]), "=r"(r[3]) : "r"(addr));
}
__device__ __forceinline__ void mma16816(float* c, const uint32_t* a,
                                         uint32_t b0, uint32_t b1)
{
    asm volatile(
        "mma.sync.aligned.m16n8k16.row.col.f32.f16.f16.f32 "
        "{%0,%1,%2,%3}, {%4,%5,%6,%7}, {%8,%9}, {%0,%1,%2,%3};\n"
        : "+f"(c[0]), "+f"(c[1]), "+f"(c[2]), "+f"(c[3])
        : "r"(a[0]), "r"(a[1]), "r"(a[2]), "r"(a[3]), "r"(b0), "r"(b1));
}
__device__ __forceinline__ void cp16(uint32_t dst, const void* src) {
    asm volatile("cp.async.cg.shared.global [%0], [%1], 16;"
                 :: "r"(dst), "l"(src));
}
#define CP_COMMIT() asm volatile("cp.async.commit_group;")
#define CP_WAIT0()  asm volatile("cp.async.wait_group 0;")

// streaming fp32x4 load (read-once data)
__device__ __forceinline__ float4 ldcs4(const float* p) {
    float4 v;
    asm volatile("ld.global.cs.v4.f32 {%0,%1,%2,%3}, [%4];"
                 : "=f"(v.x), "=f"(v.y), "=f"(v.z), "=f"(v.w) : "l"(p));
    return v;
}

// ---------------- smem layout (bytes) ---------------- (R12 proven config)
#define LDTB   80
#define OFF_A  0
#define OFF_B  10240
#define BUFB   20480
#define SMEMB  (2 * BUFB)

// ---------------------------------------------------------------------------
// W prep: W1 fp32 [512][256] -> fp16, transposed to [z][n][k].
// ---------------------------------------------------------------------------
__global__ void wprep_kernel(const float* __restrict__ W1)
{
    int idx = blockIdx.x * 256 + threadIdx.x;    // 0 .. 131071
    if (idx >= 2 * 256 * 256) return;
    int z = idx >> 16;
    int n = (idx >> 8) & 255;
    int k = idx & 255;
    g_Wt[idx] = __float2half_rn(W1[(size_t)(z * 256 + k) * 256 + n]);
}

// ---------------------------------------------------------------------------
// fp16 GEMM, fp32 accumulate — EXACT R12 body (best measured: ~130us).
// Block 128x128, BK=32, 256 threads (8 warps 4x2), warp tile 32x64, 2 CTA/SM.
// blockIdx.z: 0 -> (x_src, Wt[0], g_A, +b1), 1 -> (x_dst, Wt[1], g_B)
// ---------------------------------------------------------------------------
__global__ __launch_bounds__(256, 2)
void mma_gemm_kernel(const float* __restrict__ Xsrc,
                     const float* __restrict__ Xdst,
                     const float* __restrict__ b1,
                     int M)
{
    extern __shared__ char smem[];
    const uint32_t sb = smem_u32(smem);

    const int z = blockIdx.z;
    const float* __restrict__ X = z ? Xdst : Xsrc;
    __half* __restrict__ Out = z ? g_B : g_A;
    const __half* __restrict__ Wt = g_Wt + (size_t)z * 65536;

    const int tid  = threadIdx.x;
    const int lane = tid & 31;
    const int wid  = tid >> 5;
    const int wm   = wid & 3;
    const int wn   = wid >> 2;
    const int bm   = blockIdx.y * 128;
    const int bn   = blockIdx.x * 128;
    const bool full = (bm + 128 <= M);

    int arow[2], aseg[2];
    #pragma unroll
    for (int l = 0; l < 2; l++) {
        int f = tid + l * 256;
        arow[l] = f >> 2;
        aseg[l] = f & 3;
    }
    const int brow0 = tid >> 2,         bch0 = tid & 3;
    const int brow1 = (tid + 256) >> 2, bch1 = (tid + 256) & 3;

    float acc[2][8][4] = {};
    float4 pf0[2], pf1[2];

    auto load_A = [&](int c) {
        if (full) {
            #pragma unroll
            for (int l = 0; l < 2; l++) {
                const float* p = X + (size_t)(bm + arow[l]) * D + c * 32 + aseg[l] * 8;
                pf0[l] = ldcs4(p);
                pf1[l] = ldcs4(p + 4);
            }
        } else {
            #pragma unroll
            for (int l = 0; l < 2; l++) {
                int gr = bm + arow[l];
                pf0[l] = make_float4(0.f, 0.f, 0.f, 0.f);
                pf1[l] = pf0[l];
                if (gr < M) {
                    const float* p = X + (size_t)gr * D + c * 32 + aseg[l] * 8;
                    pf0[l] = ldcs4(p);
                    pf1[l] = ldcs4(p + 4);
                }
            }
        }
    };
    auto store_A = [&](int buf) {
        #pragma unroll
        for (int l = 0; l < 2; l++) {
            union { uint4 u; __half2 h2[4]; } v;
            v.h2[0] = __floats2half2_rn(pf0[l].x, pf0[l].y);
            v.h2[1] = __floats2half2_rn(pf0[l].z, pf0[l].w);
            v.h2[2] = __floats2half2_rn(pf1[l].x, pf1[l].y);
            v.h2[3] = __floats2half2_rn(pf1[l].z, pf1[l].w);
            *reinterpret_cast<uint4*>(
                smem + buf * BUFB + OFF_A + arow[l] * LDTB + aseg[l] * 16) = v.u;
        }
    };
    auto copy_B = [&](int c, int buf) {
        uint32_t base = sb + buf * BUFB + OFF_B;
        cp16(base + brow0 * LDTB + bch0 * 16,
             Wt + (size_t)(bn + brow0) * 256 + c * 32 + bch0 * 8);
        cp16(base + brow1 * LDTB + bch1 * 16,
             Wt + (size_t)(bn + brow1) * 256 + c * 32 + bch1 * 8);
        CP_COMMIT();
    };

    load_A(0);
    store_A(0);
    copy_B(0, 0);
    CP_WAIT0();
    __syncthreads();

    const int lrow = lane & 15;
    const int lcol = (lane >> 4) * 8;

    for (int c = 0; c < 8; c++) {
        const int buf = c & 1;
        if (c < 7) {
            copy_B(c + 1, buf ^ 1);
            load_A(c + 1);
        }

        const uint32_t b0 = sb + buf * BUFB;
        #pragma unroll
        for (int ks = 0; ks < 2; ks++) {
            const int kb = ks * 16;
            const uint32_t coff = (kb + lcol) * 2;
            uint32_t af[2][4], bf[4][4];
            #pragma unroll
            for (int i = 0; i < 2; i++)
                ldsm4(af[i], b0 + OFF_A +
                      (uint32_t)(wm * 32 + i * 16 + lrow) * LDTB + coff);
            #pragma unroll
            for (int jj = 0; jj < 4; jj++)
                ldsm4(bf[jj], b0 + OFF_B +
                      (uint32_t)(wn * 64 + jj * 16 + lrow) * LDTB + coff);
            #pragma unroll
            for (int i = 0; i < 2; i++)
                #pragma unroll
                for (int j = 0; j < 8; j++) {
                    const int jj = j >> 1, s = j & 1;
                    mma16816(acc[i][j], af[i], bf[jj][s], bf[jj][s + 2]);
                }
        }

        if (c < 7) {
            store_A(buf ^ 1);
            CP_WAIT0();
        }
        __syncthreads();
    }

    const int g  = lane >> 2;
    const int tg = lane & 3;
    #pragma unroll
    for (int i = 0; i < 2; i++)
        #pragma unroll
        for (int j = 0; j < 8; j++) {
            int r0 = bm + wm * 32 + i * 16 + g;
            int cc = bn + wn * 64 + j * 8 + tg * 2;
            float bias0 = 0.f, bias1 = 0.f;
            if (z == 0) {
                bias0 = __ldg(b1 + cc);
                bias1 = __ldg(b1 + cc + 1);
            }
            if (r0 < M)
                *reinterpret_cast<__half2*>(Out + (size_t)r0 * HID + cc) =
                    __floats2half2_rn(acc[i][j][0] + bias0, acc[i][j][1] + bias1);
            if (r0 + 8 < M)
                *reinterpret_cast<__half2*>(Out + (size_t)(r0 + 8) * HID + cc) =
                    __floats2half2_rn(acc[i][j][2] + bias0, acc[i][j][3] + bias1);
        }
}

// ---------------------------------------------------------------------------
// Edge scoring v6: R12 body + register prefetch depth 2 (pairs).
// Process 2 edges per iteration; prefetch the NEXT pair while computing the
// current pair -> 8 LDG.128 in flight per warp (2x the R12 depth).
// ---------------------------------------------------------------------------
__device__ __forceinline__ int clamp_idx(int v) {
    v = v < 0 ? 0 : v;
    return v >= NNODES ? NNODES - 1 : v;
}

__global__ __launch_bounds__(256)
void edge_score_kernel(const int* __restrict__ ei,
                       const int* __restrict__ nei,
                       const float* __restrict__ W2,
                       const float* __restrict__ b2,
                       float* __restrict__ out,
                       int E)
{
    const int lane   = threadIdx.x & 31;
    const int half   = gridDim.x >> 1;
    const bool isNeg = (int)blockIdx.x >= half;
    const int blk    = isNeg ? (int)blockIdx.x - half : (int)blockIdx.x;
    const int* __restrict__ idx = isNeg ? nei : ei;
    float* __restrict__ o       = out + (isNeg ? E : 0);

    const int warp = (blk * blockDim.x + threadIdx.x) >> 5;
    const int nw   = (half * blockDim.x) >> 5;

    float4 rw2a = *reinterpret_cast<const float4*>(W2 + lane * 8);
    float4 rw2b = *reinterpret_cast<const float4*>(W2 + lane * 8 + 4);
    float rw[8] = {rw2a.x, rw2a.y, rw2a.z, rw2a.w, rw2b.x, rw2b.y, rw2b.z, rw2b.w};
    const float bias = __ldg(b2);
    const __half2 zero = __half2half2(__float2half(0.f));

    if (warp >= E) return;

    auto load_rows = [&](int ee, uint4& au, uint4& bu) {
        int s = clamp_idx(__ldg(idx + ee));
        int d = clamp_idx(__ldg(idx + E + ee));
        au = *reinterpret_cast<const uint4*>(g_A + (size_t)s * HID + lane * 8);
        bu = *reinterpret_cast<const uint4*>(g_B + (size_t)d * HID + lane * 8);
    };
    auto score = [&](const uint4& au, const uint4& bu) {
        const __half2* ah = reinterpret_cast<const __half2*>(&au);
        const __half2* bh = reinterpret_cast<const __half2*>(&bu);
        float acc = 0.f;
        #pragma unroll
        for (int q = 0; q < 4; q++) {
            __half2 v = __hmax2(__hadd2(ah[q], bh[q]), zero);
            float2 f = __half22float2(v);
            acc = fmaf(f.x, rw[2*q],   acc);
            acc = fmaf(f.y, rw[2*q+1], acc);
        }
        #pragma unroll
        for (int oo = 16; oo; oo >>= 1)
            acc += __shfl_xor_sync(0xffffffffu, acc, oo);
        return acc + bias;
    };

    int e0 = warp;               // current pair: e0, e0+nw
    uint4 a0, b0v, a1, b1v;
    bool v0 = e0 < E;
    bool v1 = e0 + nw < E;
    if (v0) load_rows(e0,      a0, b0v);
    if (v1) load_rows(e0 + nw, a1, b1v);

    while (v0) {
        // prefetch next pair
        const int en = e0 + 2 * nw;
        const bool w0 = en < E;
        const bool w1 = en + nw < E;
        uint4 na0, nb0, na1, nb1;
        if (w0) load_rows(en,      na0, nb0);
        if (w1) load_rows(en + nw, na1, nb1);

        // compute current pair
        float s0 = score(a0, b0v);
        if (lane == 0) o[e0] = s0;
        if (v1) {
            float s1 = score(a1, b1v);
            if (lane == 0) o[e0 + nw] = s1;
        }

        e0 = en;
        v0 = w0;  v1 = w1;
        a0 = na0; b0v = nb0;
        a1 = na1; b1v = nb1;
    }
}

// ---------------------------------------------------------------------------
extern "C" void kernel_launch(void* const* d_in, const int* in_sizes, int n_in,
                              void* d_out, int out_size)
{
    const float* x_src = (const float*)d_in[0];
    const float* x_dst = (const float*)d_in[1];
    const float* W1    = (const float*)d_in[2];   // [512, 256]
    const float* b1    = (const float*)d_in[3];
    const float* W2    = (const float*)d_in[4];   // [256, 1]
    const float* b2    = (const float*)d_in[5];
    const int*   ei    = (const int*)d_in[6];     // [2, E] int32
    const int*   nei   = (const int*)d_in[7];
    float*       out   = (float*)d_out;

    const int M = in_sizes[0] / D;       // 100000
    const int E = in_sizes[6] / 2;       // 262144

    cudaFuncSetAttribute(mma_gemm_kernel,
                         cudaFuncAttributeMaxDynamicSharedMemorySize, SMEMB);

    wprep_kernel<<<(2 * 256 * 256 + 255) / 256, 256>>>(W1);

    dim3 ggrd(HID / 128, (M + 127) / 128, 2);
    mma_gemm_kernel<<<ggrd, 256, SMEMB>>>(x_src, x_dst, b1, M);

    // 4096 blocks: 16384 warps/list, 16 edges (8 pairs) per warp
    edge_score_kernel<<<4096, 256>>>(ei, nei, W2, b2, out, E);
}

// round 17
// speedup vs baseline: 1.1396x; 1.1396x over previous
#include <cuda_runtime.h>
#include <cuda_fp16.h>
#include <cstdint>

#define NNODES 100000
#define D      256
#define HID    256

// ---------------- device scratch (allocation-free rule) ----------------
__device__ __half g_A[(size_t)NNODES * HID];   // xs@W1top + b1  (fp16)
__device__ __half g_B[(size_t)NNODES * HID];   // xd@W1bot       (fp16)
// Transposed fp16 weights: Wt[z][n][k], z=0 src half, z=1 dst half
__device__ __half g_Wt[2 * 256 * 256];

// ---------------- helpers ----------------
__device__ __forceinline__ uint32_t smem_u32(const void* p) {
    uint32_t a;
    asm("{ .reg .u64 t; cvta.to.shared.u64 t, %1; cvt.u32.u64 %0, t; }"
        : "=r"(a) : "l"(p));
    return a;
}
__device__ __forceinline__ void ldsm4(uint32_t* r, uint32_t addr) {
    asm volatile("ldmatrix.sync.aligned.m8n8.x4.shared.b16 {%0,%1,%2,%3}, [%4];"
                 : "=r"(r[0]), "=r"(r[1]), "=r"(r[2]), "=r"(r[3]) : "r"(addr));
}
__device__ __forceinline__ void mma16816(float* c, const uint32_t* a,
                                         uint32_t b0, uint32_t b1)
{
    asm volatile(
        "mma.sync.aligned.m16n8k16.row.col.f32.f16.f16.f32 "
        "{%0,%1,%2,%3}, {%4,%5,%6,%7}, {%8,%9}, {%0,%1,%2,%3};\n"
        : "+f"(c[0]), "+f"(c[1]), "+f"(c[2]), "+f"(c[3])
        : "r"(a[0]), "r"(a[1]), "r"(a[2]), "r"(a[3]), "r"(b0), "r"(b1));
}
__device__ __forceinline__ void cp16(uint32_t dst, const void* src) {
    asm volatile("cp.async.cg.shared.global [%0], [%1], 16;"
                 :: "r"(dst), "l"(src));
}
#define CP_COMMIT() asm volatile("cp.async.commit_group;")
#define CP_WAIT0()  asm volatile("cp.async.wait_group 0;")

// streaming fp32x4 load (read-once data)
__device__ __forceinline__ float4 ldcs4(const float* p) {
    float4 v;
    asm volatile("ld.global.cs.v4.f32 {%0,%1,%2,%3}, [%4];"
                 : "=f"(v.x), "=f"(v.y), "=f"(v.z), "=f"(v.w) : "l"(p));
    return v;
}

// ---------------- smem layout (bytes) ---------------- (proven config)
#define LDTB   80
#define OFF_A  0
#define OFF_B  10240
#define BUFB   20480
#define SMEMB  (2 * BUFB)

// ---------------------------------------------------------------------------
// W prep: W1 fp32 [512][256] -> fp16, transposed to [z][n][k].
// ---------------------------------------------------------------------------
__global__ void wprep_kernel(const float* __restrict__ W1)
{
    int idx = blockIdx.x * 256 + threadIdx.x;    // 0 .. 131071
    if (idx >= 2 * 256 * 256) return;
    int z = idx >> 16;
    int n = (idx >> 8) & 255;
    int k = idx & 255;
    g_Wt[idx] = __float2half_rn(W1[(size_t)(z * 256 + k) * 256 + n]);
}

// ---------------------------------------------------------------------------
// fp16 GEMM, fp32 accumulate — EXACT best-measured body (R12, ~130us).
// Block 128x128, BK=32, 256 threads (8 warps 4x2), warp tile 32x64, 2 CTA/SM.
// blockIdx.z: 0 -> (x_src, Wt[0], g_A, +b1), 1 -> (x_dst, Wt[1], g_B)
// ---------------------------------------------------------------------------
__global__ __launch_bounds__(256, 2)
void mma_gemm_kernel(const float* __restrict__ Xsrc,
                     const float* __restrict__ Xdst,
                     const float* __restrict__ b1,
                     int M)
{
    extern __shared__ char smem[];
    const uint32_t sb = smem_u32(smem);

    const int z = blockIdx.z;
    const float* __restrict__ X = z ? Xdst : Xsrc;
    __half* __restrict__ Out = z ? g_B : g_A;
    const __half* __restrict__ Wt = g_Wt + (size_t)z * 65536;

    const int tid  = threadIdx.x;
    const int lane = tid & 31;
    const int wid  = tid >> 5;
    const int wm   = wid & 3;
    const int wn   = wid >> 2;
    const int bm   = blockIdx.y * 128;
    const int bn   = blockIdx.x * 128;
    const bool full = (bm + 128 <= M);

    int arow[2], aseg[2];
    #pragma unroll
    for (int l = 0; l < 2; l++) {
        int f = tid + l * 256;
        arow[l] = f >> 2;
        aseg[l] = f & 3;
    }
    const int brow0 = tid >> 2,         bch0 = tid & 3;
    const int brow1 = (tid + 256) >> 2, bch1 = (tid + 256) & 3;

    float acc[2][8][4] = {};
    float4 pf0[2], pf1[2];

    auto load_A = [&](int c) {
        if (full) {
            #pragma unroll
            for (int l = 0; l < 2; l++) {
                const float* p = X + (size_t)(bm + arow[l]) * D + c * 32 + aseg[l] * 8;
                pf0[l] = ldcs4(p);
                pf1[l] = ldcs4(p + 4);
            }
        } else {
            #pragma unroll
            for (int l = 0; l < 2; l++) {
                int gr = bm + arow[l];
                pf0[l] = make_float4(0.f, 0.f, 0.f, 0.f);
                pf1[l] = pf0[l];
                if (gr < M) {
                    const float* p = X + (size_t)gr * D + c * 32 + aseg[l] * 8;
                    pf0[l] = ldcs4(p);
                    pf1[l] = ldcs4(p + 4);
                }
            }
        }
    };
    auto store_A = [&](int buf) {
        #pragma unroll
        for (int l = 0; l < 2; l++) {
            union { uint4 u; __half2 h2[4]; } v;
            v.h2[0] = __floats2half2_rn(pf0[l].x, pf0[l].y);
            v.h2[1] = __floats2half2_rn(pf0[l].z, pf0[l].w);
            v.h2[2] = __floats2half2_rn(pf1[l].x, pf1[l].y);
            v.h2[3] = __floats2half2_rn(pf1[l].z, pf1[l].w);
            *reinterpret_cast<uint4*>(
                smem + buf * BUFB + OFF_A + arow[l] * LDTB + aseg[l] * 16) = v.u;
        }
    };
    auto copy_B = [&](int c, int buf) {
        uint32_t base = sb + buf * BUFB + OFF_B;
        cp16(base + brow0 * LDTB + bch0 * 16,
             Wt + (size_t)(bn + brow0) * 256 + c * 32 + bch0 * 8);
        cp16(base + brow1 * LDTB + bch1 * 16,
             Wt + (size_t)(bn + brow1) * 256 + c * 32 + bch1 * 8);
        CP_COMMIT();
    };

    load_A(0);
    store_A(0);
    copy_B(0, 0);
    CP_WAIT0();
    __syncthreads();

    const int lrow = lane & 15;
    const int lcol = (lane >> 4) * 8;

    for (int c = 0; c < 8; c++) {
        const int buf = c & 1;
        if (c < 7) {
            copy_B(c + 1, buf ^ 1);
            load_A(c + 1);
        }

        const uint32_t b0 = sb + buf * BUFB;
        #pragma unroll
        for (int ks = 0; ks < 2; ks++) {
            const int kb = ks * 16;
            const uint32_t coff = (kb + lcol) * 2;
            uint32_t af[2][4], bf[4][4];
            #pragma unroll
            for (int i = 0; i < 2; i++)
                ldsm4(af[i], b0 + OFF_A +
                      (uint32_t)(wm * 32 + i * 16 + lrow) * LDTB + coff);
            #pragma unroll
            for (int jj = 0; jj < 4; jj++)
                ldsm4(bf[jj], b0 + OFF_B +
                      (uint32_t)(wn * 64 + jj * 16 + lrow) * LDTB + coff);
            #pragma unroll
            for (int i = 0; i < 2; i++)
                #pragma unroll
                for (int j = 0; j < 8; j++) {
                    const int jj = j >> 1, s = j & 1;
                    mma16816(acc[i][j], af[i], bf[jj][s], bf[jj][s + 2]);
                }
        }

        if (c < 7) {
            store_A(buf ^ 1);
            CP_WAIT0();
        }
        __syncthreads();
    }

    const int g  = lane >> 2;
    const int tg = lane & 3;
    #pragma unroll
    for (int i = 0; i < 2; i++)
        #pragma unroll
        for (int j = 0; j < 8; j++) {
            int r0 = bm + wm * 32 + i * 16 + g;
            int cc = bn + wn * 64 + j * 8 + tg * 2;
            float bias0 = 0.f, bias1 = 0.f;
            if (z == 0) {
                bias0 = __ldg(b1 + cc);
                bias1 = __ldg(b1 + cc + 1);
            }
            if (r0 < M)
                *reinterpret_cast<__half2*>(Out + (size_t)r0 * HID + cc) =
                    __floats2half2_rn(acc[i][j][0] + bias0, acc[i][j][1] + bias1);
            if (r0 + 8 < M)
                *reinterpret_cast<__half2*>(Out + (size_t)(r0 + 8) * HID + cc) =
                    __floats2half2_rn(acc[i][j][2] + bias0, acc[i][j][3] + bias1);
        }
}

// ---------------------------------------------------------------------------
// Edge scoring (best-measured R12 structure, leaner addressing):
// grid-stride, registered W2, block halves pos/neg, prefetch depth 1.
// Indices are valid by construction (randint(0,N)) -> no clamp.
// Row offsets computed in 32-bit: byte offset = idx << 9 (51.2MB tables).
// ---------------------------------------------------------------------------
__global__ __launch_bounds__(256)
void edge_score_kernel(const int* __restrict__ ei,
                       const int* __restrict__ nei,
                       const float* __restrict__ W2,
                       const float* __restrict__ b2,
                       float* __restrict__ out,
                       int E)
{
    const int lane   = threadIdx.x & 31;
    const int half   = gridDim.x >> 1;
    const bool isNeg = (int)blockIdx.x >= half;
    const int blk    = isNeg ? (int)blockIdx.x - half : (int)blockIdx.x;
    const int* __restrict__ idx = isNeg ? nei : ei;
    float* __restrict__ o       = out + (isNeg ? E : 0);

    const int warp = (blk * blockDim.x + threadIdx.x) >> 5;
    const int nw   = (half * blockDim.x) >> 5;

    float4 rw2a = *reinterpret_cast<const float4*>(W2 + lane * 8);
    float4 rw2b = *reinterpret_cast<const float4*>(W2 + lane * 8 + 4);
    float rw[8] = {rw2a.x, rw2a.y, rw2a.z, rw2a.w, rw2b.x, rw2b.y, rw2b.z, rw2b.w};
    const float bias = __ldg(b2);
    const __half2 zero = __half2half2(__float2half(0.f));

    int e = warp;
    if (e >= E) return;

    // lane-constant byte base: table base + lane*16
    const char* __restrict__ baseA = reinterpret_cast<const char*>(g_A) + lane * 16;
    const char* __restrict__ baseB = reinterpret_cast<const char*>(g_B) + lane * 16;

    auto load_rows = [&](int ee, uint4& au, uint4& bu) {
        uint32_t s = (uint32_t)__ldg(idx + ee)     << 9;   // row byte offset
        uint32_t d = (uint32_t)__ldg(idx + E + ee) << 9;
        au = *reinterpret_cast<const uint4*>(baseA + s);
        bu = *reinterpret_cast<const uint4*>(baseB + d);
    };

    uint4 au, bu;
    load_rows(e, au, bu);

    while (true) {
        const int en = e + nw;
        const bool more = en < E;
        uint4 aun, bun;
        if (more)
            load_rows(en, aun, bun);

        const __half2* ah = reinterpret_cast<const __half2*>(&au);
        const __half2* bh = reinterpret_cast<const __half2*>(&bu);
        float acc = 0.f;
        #pragma unroll
        for (int q = 0; q < 4; q++) {
            __half2 v = __hmax2(__hadd2(ah[q], bh[q]), zero);
            float2 f = __half22float2(v);
            acc = fmaf(f.x, rw[2*q],   acc);
            acc = fmaf(f.y, rw[2*q+1], acc);
        }
        #pragma unroll
        for (int oo = 16; oo; oo >>= 1)
            acc += __shfl_xor_sync(0xffffffffu, acc, oo);
        if (lane == 0)
            o[e] = acc + bias;

        if (!more) break;
        e = en;
        au = aun;
        bu = bun;
    }
}

// ---------------------------------------------------------------------------
extern "C" void kernel_launch(void* const* d_in, const int* in_sizes, int n_in,
                              void* d_out, int out_size)
{
    const float* x_src = (const float*)d_in[0];
    const float* x_dst = (const float*)d_in[1];
    const float* W1    = (const float*)d_in[2];   // [512, 256]
    const float* b1    = (const float*)d_in[3];
    const float* W2    = (const float*)d_in[4];   // [256, 1]
    const float* b2    = (const float*)d_in[5];
    const int*   ei    = (const int*)d_in[6];     // [2, E] int32
    const int*   nei   = (const int*)d_in[7];
    float*       out   = (float*)d_out;

    const int M = in_sizes[0] / D;       // 100000
    const int E = in_sizes[6] / 2;       // 262144

    cudaFuncSetAttribute(mma_gemm_kernel,
                         cudaFuncAttributeMaxDynamicSharedMemorySize, SMEMB);

    wprep_kernel<<<(2 * 256 * 256 + 255) / 256, 256>>>(W1);

    dim3 ggrd(HID / 128, (M + 127) / 128, 2);
    mma_gemm_kernel<<<ggrd, 256, SMEMB>>>(x_src, x_dst, b1, M);

    edge_score_kernel<<<8192, 256>>>(ei, nei, W2, b2, out, E);
}